// round 1
// baseline (speedup 1.0000x reference)
#include <cuda_runtime.h>
#include <cuda_bf16.h>
#include <math.h>

#define D_MODEL 1024
#define N_HEADS 16
#define HEAD_DIM 64
#define BATCH 4
#define SEQ 2048
#define M_TOT (BATCH * SEQ)   // 8192

// Scratch (allocation-free rule: static __device__ globals)
__device__ float g_q[(size_t)BATCH * N_HEADS * SEQ * HEAD_DIM];
__device__ float g_k[(size_t)BATCH * N_HEADS * SEQ * HEAD_DIM];
__device__ float g_v[(size_t)BATCH * N_HEADS * SEQ * HEAD_DIM];
__device__ float g_ctx[(size_t)M_TOT * D_MODEL];

// ---------------------------------------------------------------------------
// QKV projection: for each (proj, head), out[m, e] = x[m, :] @ W[h][:, e] + b
// BM=BN=64, BK=16, 256 threads, 4x4 microtile.
// ---------------------------------------------------------------------------
__global__ __launch_bounds__(256) void qkv_gemm(
    const float* __restrict__ x,
    const float* __restrict__ Wq, const float* __restrict__ bq,
    const float* __restrict__ Wk, const float* __restrict__ bk,
    const float* __restrict__ Wv, const float* __restrict__ bv)
{
    __shared__ __align__(16) float As[16][68];   // padded, transposed A tile
    __shared__ __align__(16) float Bs[16][64];

    const int y    = blockIdx.y;          // 0..47
    const int proj = y >> 4;
    const int h    = y & 15;

    const float* W;
    const float* bias;
    float* out;
    if (proj == 0)      { W = Wq; bias = bq; out = g_q; }
    else if (proj == 1) { W = Wk; bias = bk; out = g_k; }
    else                { W = Wv; bias = bv; out = g_v; }
    W    += (size_t)h * D_MODEL * HEAD_DIM;
    bias += h * HEAD_DIM;

    const int tid = threadIdx.x;
    const int tx  = tid & 15;
    const int ty  = tid >> 4;
    const int m0  = blockIdx.x * 64;

    const int aRow = tid >> 2;         // 0..63
    const int aC4  = (tid & 3) * 4;    // 0,4,8,12
    const int bRow = tid >> 4;         // 0..15
    const int bC4  = (tid & 15) * 4;   // 0..60

    float acc[4][4] = {};

    for (int k0 = 0; k0 < D_MODEL; k0 += 16) {
        float4 a4 = *(const float4*)(x + (size_t)(m0 + aRow) * D_MODEL + k0 + aC4);
        As[aC4 + 0][aRow] = a4.x;
        As[aC4 + 1][aRow] = a4.y;
        As[aC4 + 2][aRow] = a4.z;
        As[aC4 + 3][aRow] = a4.w;
        *(float4*)&Bs[bRow][bC4] =
            *(const float4*)(W + (size_t)(k0 + bRow) * HEAD_DIM + bC4);
        __syncthreads();

        #pragma unroll
        for (int k = 0; k < 16; k++) {
            float4 ra = *(const float4*)&As[k][ty * 4];
            float4 rb = *(const float4*)&Bs[k][tx * 4];
            float ar[4] = {ra.x, ra.y, ra.z, ra.w};
            float br[4] = {rb.x, rb.y, rb.z, rb.w};
            #pragma unroll
            for (int i = 0; i < 4; i++)
                #pragma unroll
                for (int j = 0; j < 4; j++)
                    acc[i][j] += ar[i] * br[j];
        }
        __syncthreads();
    }

    #pragma unroll
    for (int i = 0; i < 4; i++) {
        int m = m0 + ty * 4 + i;
        int b = m / SEQ;
        int l = m % SEQ;
        float* orow = out + (((size_t)(b * N_HEADS + h)) * SEQ + l) * HEAD_DIM;
        #pragma unroll
        for (int j = 0; j < 4; j++) {
            int e = tx * 4 + j;
            orow[e] = acc[i][j] + bias[e];
        }
    }
}

// ---------------------------------------------------------------------------
// RoPE on g_q / g_k. One thread per (bh, l, i) pair, i in [0,32).
// ---------------------------------------------------------------------------
__global__ __launch_bounds__(256) void rope_kernel()
{
    int idx = blockIdx.x * blockDim.x + threadIdx.x;   // < 64*2048*32
    int i  = idx & 31;
    int l  = (idx >> 5) & (SEQ - 1);
    int bh = idx >> 16;

    float inv_freq = 1.0f / powf(10000.0f, (float)i / 32.0f);
    float ang = (float)l * inv_freq;
    float s, c;
    sincosf(ang, &s, &c);

    size_t base = ((size_t)bh * SEQ + l) * HEAD_DIM;
    float q1 = g_q[base + i], q2 = g_q[base + i + 32];
    g_q[base + i]      = q1 * c - q2 * s;
    g_q[base + i + 32] = q1 * s + q2 * c;
    float k1 = g_k[base + i], k2 = g_k[base + i + 32];
    g_k[base + i]      = k1 * c - k2 * s;
    g_k[base + i + 32] = k1 * s + k2 * c;
}

// ---------------------------------------------------------------------------
// Attention: 1 thread = 1 query row. 128 rows per block. 32-key tiles in smem.
// Online softmax, fp32 accumulate in registers. Writes merged ctx [M, 1024].
// ---------------------------------------------------------------------------
__global__ __launch_bounds__(128) void attn_kernel()
{
    __shared__ __align__(16) float ks[32][64];
    __shared__ __align__(16) float vs[32][64];

    const int tid = threadIdx.x;
    const int bh  = blockIdx.y;                 // b*H + h
    const int lq  = blockIdx.x * 128 + tid;     // query row in [0, SEQ)
    const float scale = 0.125f;                 // 1/sqrt(64)

    const float* qp = g_q + ((size_t)bh * SEQ + lq) * HEAD_DIM;
    float4 q[16];
    #pragma unroll
    for (int i = 0; i < 16; i++) {
        q[i] = *(const float4*)(qp + i * 4);
        q[i].x *= scale; q[i].y *= scale; q[i].z *= scale; q[i].w *= scale;
    }

    const float* kbase = g_k + (size_t)bh * SEQ * HEAD_DIM;
    const float* vbase = g_v + (size_t)bh * SEQ * HEAD_DIM;

    float m_run = -1e30f;
    float lsum  = 0.0f;
    float4 acc[16] = {};

    for (int t = 0; t < SEQ / 32; t++) {
        __syncthreads();
        #pragma unroll
        for (int i = 0; i < 4; i++) {
            int f  = tid + i * 128;        // 0..511
            int r  = f >> 4;
            int c4 = (f & 15) * 4;
            *(float4*)&ks[r][c4] = *(const float4*)(kbase + (size_t)(t * 32 + r) * HEAD_DIM + c4);
            *(float4*)&vs[r][c4] = *(const float4*)(vbase + (size_t)(t * 32 + r) * HEAD_DIM + c4);
        }
        __syncthreads();

        float s[32];
        float tmax = -1e30f;
        #pragma unroll
        for (int j = 0; j < 32; j++) {
            float sum = 0.0f;
            #pragma unroll
            for (int i = 0; i < 16; i++) {
                float4 kv = *(const float4*)&ks[j][i * 4];
                sum += q[i].x * kv.x + q[i].y * kv.y + q[i].z * kv.z + q[i].w * kv.w;
            }
            s[j] = sum;
            tmax = fmaxf(tmax, sum);
        }

        float mnew = fmaxf(m_run, tmax);
        float corr = __expf(m_run - mnew);
        m_run = mnew;
        lsum *= corr;
        #pragma unroll
        for (int i = 0; i < 16; i++) {
            acc[i].x *= corr; acc[i].y *= corr; acc[i].z *= corr; acc[i].w *= corr;
        }
        #pragma unroll
        for (int j = 0; j < 32; j++) {
            float p = __expf(s[j] - m_run);
            lsum += p;
            #pragma unroll
            for (int i = 0; i < 16; i++) {
                float4 vv = *(const float4*)&vs[j][i * 4];
                acc[i].x += p * vv.x; acc[i].y += p * vv.y;
                acc[i].z += p * vv.z; acc[i].w += p * vv.w;
            }
        }
    }

    float inv = 1.0f / lsum;
    int b = bh >> 4;
    int h = bh & 15;
    float* op = g_ctx + ((size_t)(b * SEQ + lq)) * D_MODEL + h * HEAD_DIM;
    #pragma unroll
    for (int i = 0; i < 16; i++) {
        float4 o = acc[i];
        o.x *= inv; o.y *= inv; o.z *= inv; o.w *= inv;
        *(float4*)(op + i * 4) = o;
    }
}

// ---------------------------------------------------------------------------
// Output projection: out[m, n] = ctx[m, :] @ Wo[:, n] + bo[n]
// Same tiling as qkv_gemm, Wo is [1024,1024] row-major.
// ---------------------------------------------------------------------------
__global__ __launch_bounds__(256) void out_gemm(
    const float* __restrict__ Wo, const float* __restrict__ bo,
    float* __restrict__ out)
{
    __shared__ __align__(16) float As[16][68];
    __shared__ __align__(16) float Bs[16][64];

    const int tid = threadIdx.x;
    const int tx  = tid & 15;
    const int ty  = tid >> 4;
    const int m0  = blockIdx.x * 64;
    const int n0  = blockIdx.y * 64;

    const int aRow = tid >> 2;
    const int aC4  = (tid & 3) * 4;
    const int bRow = tid >> 4;
    const int bC4  = (tid & 15) * 4;

    float acc[4][4] = {};

    for (int k0 = 0; k0 < D_MODEL; k0 += 16) {
        float4 a4 = *(const float4*)(g_ctx + (size_t)(m0 + aRow) * D_MODEL + k0 + aC4);
        As[aC4 + 0][aRow] = a4.x;
        As[aC4 + 1][aRow] = a4.y;
        As[aC4 + 2][aRow] = a4.z;
        As[aC4 + 3][aRow] = a4.w;
        *(float4*)&Bs[bRow][bC4] =
            *(const float4*)(Wo + (size_t)(k0 + bRow) * D_MODEL + n0 + bC4);
        __syncthreads();

        #pragma unroll
        for (int k = 0; k < 16; k++) {
            float4 ra = *(const float4*)&As[k][ty * 4];
            float4 rb = *(const float4*)&Bs[k][tx * 4];
            float ar[4] = {ra.x, ra.y, ra.z, ra.w};
            float br[4] = {rb.x, rb.y, rb.z, rb.w};
            #pragma unroll
            for (int i = 0; i < 4; i++)
                #pragma unroll
                for (int j = 0; j < 4; j++)
                    acc[i][j] += ar[i] * br[j];
        }
        __syncthreads();
    }

    #pragma unroll
    for (int i = 0; i < 4; i++) {
        int m = m0 + ty * 4 + i;
        #pragma unroll
        for (int j = 0; j < 4; j++) {
            int n = n0 + tx * 4 + j;
            out[(size_t)m * D_MODEL + n] = acc[i][j] + bo[n];
        }
    }
}

// ---------------------------------------------------------------------------
extern "C" void kernel_launch(void* const* d_in, const int* in_sizes, int n_in,
                              void* d_out, int out_size)
{
    const float* x  = (const float*)d_in[0];
    const float* Wq = (const float*)d_in[1];
    const float* bq = (const float*)d_in[2];
    const float* Wk = (const float*)d_in[3];
    const float* bk = (const float*)d_in[4];
    const float* Wv = (const float*)d_in[5];
    const float* bv = (const float*)d_in[6];
    const float* Wo = (const float*)d_in[7];
    const float* bo = (const float*)d_in[8];
    float* out = (float*)d_out;

    qkv_gemm<<<dim3(M_TOT / 64, 48), 256>>>(x, Wq, bq, Wk, bk, Wv, bv);
    rope_kernel<<<(BATCH * N_HEADS * SEQ * 32) / 256, 256>>>();
    attn_kernel<<<dim3(SEQ / 128, BATCH * N_HEADS), 128>>>();
    out_gemm<<<dim3(M_TOT / 64, D_MODEL / 64), 256>>>(Wo, bo, out);
}

// round 3
// speedup vs baseline: 3.0437x; 3.0437x over previous
#include <cuda_runtime.h>
#include <cuda_bf16.h>
#include <math.h>
#include <stdint.h>

#define D_MODEL 1024
#define N_HEADS 16
#define HEAD_DIM 64
#define BATCH 4
#define SEQ 2048
#define M_TOT (BATCH * SEQ)   // 8192

// Scratch (allocation-free rule: static __device__ globals)
__device__ float g_q[(size_t)BATCH * N_HEADS * SEQ * HEAD_DIM];
__device__ float g_k[(size_t)BATCH * N_HEADS * SEQ * HEAD_DIM];
__device__ float g_v[(size_t)BATCH * N_HEADS * SEQ * HEAD_DIM];
__device__ float g_ctx[(size_t)M_TOT * D_MODEL];

// ---------------------------------------------------------------------------
// tf32 helpers
// ---------------------------------------------------------------------------
__device__ __forceinline__ uint32_t f2t(float f) {
    uint32_t r;
    asm("cvt.rna.tf32.f32 %0, %1;" : "=r"(r) : "f"(f));
    return r;
}

#define MMA_TF32(d, a, b)                                                     \
    asm volatile(                                                             \
        "mma.sync.aligned.m16n8k8.row.col.f32.tf32.tf32.f32 "                 \
        "{%0,%1,%2,%3},{%4,%5,%6,%7},{%8,%9},{%0,%1,%2,%3};"                  \
        : "+f"((d)[0]), "+f"((d)[1]), "+f"((d)[2]), "+f"((d)[3])              \
        : "r"((a)[0]), "r"((a)[1]), "r"((a)[2]), "r"((a)[3]),                 \
          "r"((b)[0]), "r"((b)[1]))

// ---------------------------------------------------------------------------
// QKV projection (tf32 tensor cores).
// Per (proj, head): C[8192x64] = X[8192x1024] @ W[1024x64] + b
// BM=128, BN=64, BK=32. 256 threads, 8 warps in 4(M) x 2(N), warp tile 32x32.
// ---------------------------------------------------------------------------
__global__ __launch_bounds__(256) void qkv_gemm_tc(
    const float* __restrict__ x,
    const float* __restrict__ Wq, const float* __restrict__ bq,
    const float* __restrict__ Wk, const float* __restrict__ bk,
    const float* __restrict__ Wv, const float* __restrict__ bv)
{
    __shared__ uint32_t As[128][36];   // [m][k] tf32, pad 36
    __shared__ uint32_t Bs[32][68];    // [k][n] tf32, pad 68

    const int y    = blockIdx.y;       // 0..47
    const int proj = y >> 4;
    const int h    = y & 15;

    const float* W; const float* bias; float* out;
    if (proj == 0)      { W = Wq; bias = bq; out = g_q; }
    else if (proj == 1) { W = Wk; bias = bk; out = g_k; }
    else                { W = Wv; bias = bv; out = g_v; }
    W    += (size_t)h * D_MODEL * HEAD_DIM;
    bias += h * HEAD_DIM;

    const int tid  = threadIdx.x;
    const int warp = tid >> 5;
    const int lane = tid & 31;
    const int wm   = warp >> 1;        // 0..3
    const int wn   = warp & 1;         // 0..1
    const int gid  = lane >> 2;        // 0..7
    const int tig  = lane & 3;         // 0..3
    const int m0   = blockIdx.x * 128;

    float acc[2][4][4] = {};

    for (int k0 = 0; k0 < D_MODEL; k0 += 32) {
        __syncthreads();
        // A tile: 128x32 = 1024 float4, 4 per thread
        #pragma unroll
        for (int i = 0; i < 4; i++) {
            int f = tid + i * 256;
            int r = f >> 3;
            int c = (f & 7) * 4;
            float4 a = *(const float4*)(x + (size_t)(m0 + r) * D_MODEL + k0 + c);
            uint4 t = { f2t(a.x), f2t(a.y), f2t(a.z), f2t(a.w) };
            *(uint4*)&As[r][c] = t;
        }
        // B tile: 32x64 = 512 float4, 2 per thread
        #pragma unroll
        for (int i = 0; i < 2; i++) {
            int f = tid + i * 256;
            int r = f >> 4;
            int c = (f & 15) * 4;
            float4 b = *(const float4*)(W + (size_t)(k0 + r) * HEAD_DIM + c);
            uint4 t = { f2t(b.x), f2t(b.y), f2t(b.z), f2t(b.w) };
            *(uint4*)&Bs[r][c] = t;
        }
        __syncthreads();

        #pragma unroll
        for (int ks = 0; ks < 4; ks++) {
            const int kk = ks * 8;
            uint32_t a[2][4], b[4][2];
            #pragma unroll
            for (int mt = 0; mt < 2; mt++) {
                const int mr = wm * 32 + mt * 16;
                a[mt][0] = As[mr + gid][kk + tig];
                a[mt][1] = As[mr + gid + 8][kk + tig];
                a[mt][2] = As[mr + gid][kk + tig + 4];
                a[mt][3] = As[mr + gid + 8][kk + tig + 4];
            }
            #pragma unroll
            for (int nt = 0; nt < 4; nt++) {
                const int nc = wn * 32 + nt * 8;
                b[nt][0] = Bs[kk + tig][nc + gid];
                b[nt][1] = Bs[kk + tig + 4][nc + gid];
            }
            #pragma unroll
            for (int mt = 0; mt < 2; mt++)
                #pragma unroll
                for (int nt = 0; nt < 4; nt++)
                    MMA_TF32(acc[mt][nt], a[mt], b[nt]);
        }
    }

    // Epilogue: write to [b][h][l][e]
    #pragma unroll
    for (int mt = 0; mt < 2; mt++) {
        #pragma unroll
        for (int r2 = 0; r2 < 2; r2++) {
            int m = m0 + wm * 32 + mt * 16 + gid + r2 * 8;
            int b = m >> 11;
            int l = m & (SEQ - 1);
            float* orow = out + (((size_t)(b * N_HEADS + h)) * SEQ + l) * HEAD_DIM;
            #pragma unroll
            for (int nt = 0; nt < 4; nt++) {
                int col = wn * 32 + nt * 8 + tig * 2;
                float2 v;
                v.x = acc[mt][nt][r2 * 2 + 0] + bias[col];
                v.y = acc[mt][nt][r2 * 2 + 1] + bias[col + 1];
                *(float2*)(orow + col) = v;
            }
        }
    }
}

// ---------------------------------------------------------------------------
// RoPE on g_q / g_k. One thread per (bh, l, i) pair, i in [0,32).
// ---------------------------------------------------------------------------
__global__ __launch_bounds__(256) void rope_kernel()
{
    int idx = blockIdx.x * blockDim.x + threadIdx.x;
    int i  = idx & 31;
    int l  = (idx >> 5) & (SEQ - 1);
    int bh = idx >> 16;

    float inv_freq = __powf(10000.0f, -(float)i / 32.0f);
    float ang = (float)l * inv_freq;
    float s, c;
    __sincosf(ang, &s, &c);

    size_t base = ((size_t)bh * SEQ + l) * HEAD_DIM;
    float q1 = g_q[base + i], q2 = g_q[base + i + 32];
    g_q[base + i]      = q1 * c - q2 * s;
    g_q[base + i + 32] = q1 * s + q2 * c;
    float k1 = g_k[base + i], k2 = g_k[base + i + 32];
    g_k[base + i]      = k1 * c - k2 * s;
    g_k[base + i + 32] = k1 * s + k2 * c;
}

// ---------------------------------------------------------------------------
// Flash attention, tf32 tensor cores.
// Br=64 queries per block (4 warps x 16 rows), Bc=64 keys per tile.
// K smem tile is reused to hold P (K is dead after S is computed).
// ---------------------------------------------------------------------------
__global__ __launch_bounds__(128) void attn_tc()
{
    __shared__ uint32_t KP[64][68];   // K tile [key][dim], then P [query][key]
    __shared__ uint32_t Vs[64][68];   // V tile [key][dim]

    const int tid  = threadIdx.x;
    const int warp = tid >> 5;
    const int lane = tid & 31;
    const int gid  = lane >> 2;
    const int tig  = lane & 3;
    const int bh   = blockIdx.y;
    const int q0   = blockIdx.x * 64 + warp * 16;

    // Q fragments in registers, pre-scaled by 1/sqrt(64)
    const float* qr0 = g_q + ((size_t)bh * SEQ + q0 + gid) * HEAD_DIM;
    const float* qr1 = qr0 + 8 * HEAD_DIM;
    uint32_t qa[8][4];
    #pragma unroll
    for (int ks = 0; ks < 8; ks++) {
        qa[ks][0] = f2t(qr0[ks * 8 + tig] * 0.125f);
        qa[ks][1] = f2t(qr1[ks * 8 + tig] * 0.125f);
        qa[ks][2] = f2t(qr0[ks * 8 + tig + 4] * 0.125f);
        qa[ks][3] = f2t(qr1[ks * 8 + tig + 4] * 0.125f);
    }

    const float* kb = g_k + (size_t)bh * SEQ * HEAD_DIM;
    const float* vb = g_v + (size_t)bh * SEQ * HEAD_DIM;

    float oacc[8][4] = {};
    float mr0 = -1e30f, mr1 = -1e30f;
    float l0 = 0.0f, l1 = 0.0f;

    for (int t = 0; t < SEQ / 64; t++) {
        __syncthreads();
        // Load K, V tiles (64x64 each = 1024 float4 each; 8 per thread)
        #pragma unroll
        for (int i = 0; i < 8; i++) {
            int f = tid + i * 128;
            int r = f >> 4;
            int c = (f & 15) * 4;
            float4 k4 = *(const float4*)(kb + (size_t)(t * 64 + r) * HEAD_DIM + c);
            uint4 kt = { f2t(k4.x), f2t(k4.y), f2t(k4.z), f2t(k4.w) };
            *(uint4*)&KP[r][c] = kt;
            float4 v4 = *(const float4*)(vb + (size_t)(t * 64 + r) * HEAD_DIM + c);
            uint4 vt = { f2t(v4.x), f2t(v4.y), f2t(v4.z), f2t(v4.w) };
            *(uint4*)&Vs[r][c] = vt;
        }
        __syncthreads();

        // S = Q @ K^T   (M=16 per warp, N=64 keys, K=64 dims)
        float s[8][4] = {};
        #pragma unroll
        for (int ks = 0; ks < 8; ks++) {
            const int kk = ks * 8;
            #pragma unroll
            for (int nt = 0; nt < 8; nt++) {
                uint32_t b[2];
                b[0] = KP[nt * 8 + gid][kk + tig];
                b[1] = KP[nt * 8 + gid][kk + tig + 4];
                MMA_TF32(s[nt], qa[ks], b);
            }
        }

        // Online softmax (rows: q0+gid and q0+gid+8)
        float mx0 = -1e30f, mx1 = -1e30f;
        #pragma unroll
        for (int nt = 0; nt < 8; nt++) {
            mx0 = fmaxf(mx0, fmaxf(s[nt][0], s[nt][1]));
            mx1 = fmaxf(mx1, fmaxf(s[nt][2], s[nt][3]));
        }
        mx0 = fmaxf(mx0, __shfl_xor_sync(0xffffffff, mx0, 1));
        mx0 = fmaxf(mx0, __shfl_xor_sync(0xffffffff, mx0, 2));
        mx1 = fmaxf(mx1, __shfl_xor_sync(0xffffffff, mx1, 1));
        mx1 = fmaxf(mx1, __shfl_xor_sync(0xffffffff, mx1, 2));

        float nm0 = fmaxf(mr0, mx0);
        float nm1 = fmaxf(mr1, mx1);
        float cf0 = __expf(mr0 - nm0);
        float cf1 = __expf(mr1 - nm1);
        mr0 = nm0; mr1 = nm1;

        float rs0 = 0.0f, rs1 = 0.0f;
        #pragma unroll
        for (int nt = 0; nt < 8; nt++) {
            s[nt][0] = __expf(s[nt][0] - nm0);
            s[nt][1] = __expf(s[nt][1] - nm0);
            s[nt][2] = __expf(s[nt][2] - nm1);
            s[nt][3] = __expf(s[nt][3] - nm1);
            rs0 += s[nt][0] + s[nt][1];
            rs1 += s[nt][2] + s[nt][3];
        }
        rs0 += __shfl_xor_sync(0xffffffff, rs0, 1);
        rs0 += __shfl_xor_sync(0xffffffff, rs0, 2);
        rs1 += __shfl_xor_sync(0xffffffff, rs1, 1);
        rs1 += __shfl_xor_sync(0xffffffff, rs1, 2);
        l0 = l0 * cf0 + rs0;
        l1 = l1 * cf1 + rs1;

        #pragma unroll
        for (int nt = 0; nt < 8; nt++) {
            oacc[nt][0] *= cf0; oacc[nt][1] *= cf0;
            oacc[nt][2] *= cf1; oacc[nt][3] *= cf1;
        }

        __syncthreads();   // everyone done reading K before overwrite with P
        // Store P (tf32) into KP as [query][key]
        const int pr0 = warp * 16 + gid;
        #pragma unroll
        for (int nt = 0; nt < 8; nt++) {
            int col = nt * 8 + tig * 2;
            KP[pr0][col]         = f2t(s[nt][0]);
            KP[pr0][col + 1]     = f2t(s[nt][1]);
            KP[pr0 + 8][col]     = f2t(s[nt][2]);
            KP[pr0 + 8][col + 1] = f2t(s[nt][3]);
        }
        __syncthreads();

        // O += P @ V   (M=16 per warp, N=64 dims, K=64 keys)
        #pragma unroll
        for (int ks = 0; ks < 8; ks++) {
            const int kk = ks * 8;
            uint32_t pa[4];
            pa[0] = KP[pr0][kk + tig];
            pa[1] = KP[pr0 + 8][kk + tig];
            pa[2] = KP[pr0][kk + tig + 4];
            pa[3] = KP[pr0 + 8][kk + tig + 4];
            #pragma unroll
            for (int nt = 0; nt < 8; nt++) {
                uint32_t vbf[2];
                vbf[0] = Vs[kk + tig][nt * 8 + gid];
                vbf[1] = Vs[kk + tig + 4][nt * 8 + gid];
                MMA_TF32(oacc[nt], pa, vbf);
            }
        }
    }

    // Normalize + write merged ctx [b*SEQ+l][h*64+col]
    float inv0 = 1.0f / l0;
    float inv1 = 1.0f / l1;
    int b = bh >> 4;
    int h = bh & 15;
    int row0 = blockIdx.x * 64 + warp * 16 + gid;
    float* o0 = g_ctx + ((size_t)(b * SEQ + row0)) * D_MODEL + h * HEAD_DIM;
    float* o1 = g_ctx + ((size_t)(b * SEQ + row0 + 8)) * D_MODEL + h * HEAD_DIM;
    #pragma unroll
    for (int nt = 0; nt < 8; nt++) {
        int col = nt * 8 + tig * 2;
        float2 v0 = { oacc[nt][0] * inv0, oacc[nt][1] * inv0 };
        float2 v1 = { oacc[nt][2] * inv1, oacc[nt][3] * inv1 };
        *(float2*)(o0 + col) = v0;
        *(float2*)(o1 + col) = v1;
    }
}

// ---------------------------------------------------------------------------
// Output projection (tf32): out[8192x1024] = ctx @ Wo + bo
// Same tiling as qkv_gemm_tc. Grid (64, 16).
// ---------------------------------------------------------------------------
__global__ __launch_bounds__(256) void out_gemm_tc(
    const float* __restrict__ Wo, const float* __restrict__ bo,
    float* __restrict__ out)
{
    __shared__ uint32_t As[128][36];
    __shared__ uint32_t Bs[32][68];

    const int tid  = threadIdx.x;
    const int warp = tid >> 5;
    const int lane = tid & 31;
    const int wm   = warp >> 1;
    const int wn   = warp & 1;
    const int gid  = lane >> 2;
    const int tig  = lane & 3;
    const int m0   = blockIdx.x * 128;
    const int n0   = blockIdx.y * 64;

    float acc[2][4][4] = {};

    for (int k0 = 0; k0 < D_MODEL; k0 += 32) {
        __syncthreads();
        #pragma unroll
        for (int i = 0; i < 4; i++) {
            int f = tid + i * 256;
            int r = f >> 3;
            int c = (f & 7) * 4;
            float4 a = *(const float4*)(g_ctx + (size_t)(m0 + r) * D_MODEL + k0 + c);
            uint4 t = { f2t(a.x), f2t(a.y), f2t(a.z), f2t(a.w) };
            *(uint4*)&As[r][c] = t;
        }
        #pragma unroll
        for (int i = 0; i < 2; i++) {
            int f = tid + i * 256;
            int r = f >> 4;
            int c = (f & 15) * 4;
            float4 b = *(const float4*)(Wo + (size_t)(k0 + r) * D_MODEL + n0 + c);
            uint4 t = { f2t(b.x), f2t(b.y), f2t(b.z), f2t(b.w) };
            *(uint4*)&Bs[r][c] = t;
        }
        __syncthreads();

        #pragma unroll
        for (int ks = 0; ks < 4; ks++) {
            const int kk = ks * 8;
            uint32_t a[2][4], b[4][2];
            #pragma unroll
            for (int mt = 0; mt < 2; mt++) {
                const int mr = wm * 32 + mt * 16;
                a[mt][0] = As[mr + gid][kk + tig];
                a[mt][1] = As[mr + gid + 8][kk + tig];
                a[mt][2] = As[mr + gid][kk + tig + 4];
                a[mt][3] = As[mr + gid + 8][kk + tig + 4];
            }
            #pragma unroll
            for (int nt = 0; nt < 4; nt++) {
                const int nc = wn * 32 + nt * 8;
                b[nt][0] = Bs[kk + tig][nc + gid];
                b[nt][1] = Bs[kk + tig + 4][nc + gid];
            }
            #pragma unroll
            for (int mt = 0; mt < 2; mt++)
                #pragma unroll
                for (int nt = 0; nt < 4; nt++)
                    MMA_TF32(acc[mt][nt], a[mt], b[nt]);
        }
    }

    #pragma unroll
    for (int mt = 0; mt < 2; mt++) {
        #pragma unroll
        for (int r2 = 0; r2 < 2; r2++) {
            int m = m0 + wm * 32 + mt * 16 + gid + r2 * 8;
            #pragma unroll
            for (int nt = 0; nt < 4; nt++) {
                int n = n0 + wn * 32 + nt * 8 + tig * 2;
                float2 v;
                v.x = acc[mt][nt][r2 * 2 + 0] + bo[n];
                v.y = acc[mt][nt][r2 * 2 + 1] + bo[n + 1];
                *(float2*)(out + (size_t)m * D_MODEL + n) = v;
            }
        }
    }
}

// ---------------------------------------------------------------------------
extern "C" void kernel_launch(void* const* d_in, const int* in_sizes, int n_in,
                              void* d_out, int out_size)
{
    const float* x  = (const float*)d_in[0];
    const float* Wq = (const float*)d_in[1];
    const float* bq = (const float*)d_in[2];
    const float* Wk = (const float*)d_in[3];
    const float* bk = (const float*)d_in[4];
    const float* Wv = (const float*)d_in[5];
    const float* bv = (const float*)d_in[6];
    const float* Wo = (const float*)d_in[7];
    const float* bo = (const float*)d_in[8];
    float* out = (float*)d_out;

    qkv_gemm_tc<<<dim3(M_TOT / 128, 48), 256>>>(x, Wq, bq, Wk, bk, Wv, bv);
    rope_kernel<<<(BATCH * N_HEADS * SEQ * 32) / 256, 256>>>();
    attn_tc<<<dim3(SEQ / 64, BATCH * N_HEADS), 128>>>();
    out_gemm_tc<<<dim3(M_TOT / 128, D_MODEL / 64), 256>>>(Wo, bo, out);
}

// round 4
// speedup vs baseline: 3.0439x; 1.0001x over previous
#include <cuda_runtime.h>
#include <cuda_bf16.h>
#include <math.h>
#include <stdint.h>

#define D_MODEL 1024
#define N_HEADS 16
#define HEAD_DIM 64
#define BATCH 4
#define SEQ 2048
#define M_TOT (BATCH * SEQ)   // 8192

// Scratch (allocation-free rule: static __device__ globals)
__device__ float g_q[(size_t)BATCH * N_HEADS * SEQ * HEAD_DIM];
__device__ float g_k[(size_t)BATCH * N_HEADS * SEQ * HEAD_DIM];
__device__ float g_v[(size_t)BATCH * N_HEADS * SEQ * HEAD_DIM];
__device__ float g_ctx[(size_t)M_TOT * D_MODEL];

// ---------------------------------------------------------------------------
// tf32 helpers
// ---------------------------------------------------------------------------
__device__ __forceinline__ uint32_t f2t(float f) {
    uint32_t r;
    asm("cvt.rna.tf32.f32 %0, %1;" : "=r"(r) : "f"(f));
    return r;
}

#define MMA_TF32(d, a, b)                                                     \
    asm volatile(                                                             \
        "mma.sync.aligned.m16n8k8.row.col.f32.tf32.tf32.f32 "                 \
        "{%0,%1,%2,%3},{%4,%5,%6,%7},{%8,%9},{%0,%1,%2,%3};"                  \
        : "+f"((d)[0]), "+f"((d)[1]), "+f"((d)[2]), "+f"((d)[3])              \
        : "r"((a)[0]), "r"((a)[1]), "r"((a)[2]), "r"((a)[3]),                 \
          "r"((b)[0]), "r"((b)[1]))

// ---------------------------------------------------------------------------
// QKV projection (tf32 tensor cores).
// Per (proj, head): C[8192x64] = X[8192x1024] @ W[1024x64] + b
// BM=128, BN=64, BK=32. 256 threads, 8 warps in 4(M) x 2(N), warp tile 32x32.
// ---------------------------------------------------------------------------
__global__ __launch_bounds__(256) void qkv_gemm_tc(
    const float* __restrict__ x,
    const float* __restrict__ Wq, const float* __restrict__ bq,
    const float* __restrict__ Wk, const float* __restrict__ bk,
    const float* __restrict__ Wv, const float* __restrict__ bv)
{
    __shared__ uint32_t As[128][36];   // [m][k] tf32, pad 36
    __shared__ uint32_t Bs[32][68];    // [k][n] tf32, pad 68

    const int y    = blockIdx.y;       // 0..47
    const int proj = y >> 4;
    const int h    = y & 15;

    const float* W; const float* bias; float* out;
    if (proj == 0)      { W = Wq; bias = bq; out = g_q; }
    else if (proj == 1) { W = Wk; bias = bk; out = g_k; }
    else                { W = Wv; bias = bv; out = g_v; }
    W    += (size_t)h * D_MODEL * HEAD_DIM;
    bias += h * HEAD_DIM;

    const int tid  = threadIdx.x;
    const int warp = tid >> 5;
    const int lane = tid & 31;
    const int wm   = warp >> 1;        // 0..3
    const int wn   = warp & 1;         // 0..1
    const int gid  = lane >> 2;        // 0..7
    const int tig  = lane & 3;         // 0..3
    const int m0   = blockIdx.x * 128;

    float acc[2][4][4] = {};

    for (int k0 = 0; k0 < D_MODEL; k0 += 32) {
        __syncthreads();
        // A tile: 128x32 = 1024 float4, 4 per thread
        #pragma unroll
        for (int i = 0; i < 4; i++) {
            int f = tid + i * 256;
            int r = f >> 3;
            int c = (f & 7) * 4;
            float4 a = *(const float4*)(x + (size_t)(m0 + r) * D_MODEL + k0 + c);
            uint4 t = { f2t(a.x), f2t(a.y), f2t(a.z), f2t(a.w) };
            *(uint4*)&As[r][c] = t;
        }
        // B tile: 32x64 = 512 float4, 2 per thread
        #pragma unroll
        for (int i = 0; i < 2; i++) {
            int f = tid + i * 256;
            int r = f >> 4;
            int c = (f & 15) * 4;
            float4 b = *(const float4*)(W + (size_t)(k0 + r) * HEAD_DIM + c);
            uint4 t = { f2t(b.x), f2t(b.y), f2t(b.z), f2t(b.w) };
            *(uint4*)&Bs[r][c] = t;
        }
        __syncthreads();

        #pragma unroll
        for (int ks = 0; ks < 4; ks++) {
            const int kk = ks * 8;
            uint32_t a[2][4], b[4][2];
            #pragma unroll
            for (int mt = 0; mt < 2; mt++) {
                const int mr = wm * 32 + mt * 16;
                a[mt][0] = As[mr + gid][kk + tig];
                a[mt][1] = As[mr + gid + 8][kk + tig];
                a[mt][2] = As[mr + gid][kk + tig + 4];
                a[mt][3] = As[mr + gid + 8][kk + tig + 4];
            }
            #pragma unroll
            for (int nt = 0; nt < 4; nt++) {
                const int nc = wn * 32 + nt * 8;
                b[nt][0] = Bs[kk + tig][nc + gid];
                b[nt][1] = Bs[kk + tig + 4][nc + gid];
            }
            #pragma unroll
            for (int mt = 0; mt < 2; mt++)
                #pragma unroll
                for (int nt = 0; nt < 4; nt++)
                    MMA_TF32(acc[mt][nt], a[mt], b[nt]);
        }
    }

    // Epilogue: write to [b][h][l][e]
    #pragma unroll
    for (int mt = 0; mt < 2; mt++) {
        #pragma unroll
        for (int r2 = 0; r2 < 2; r2++) {
            int m = m0 + wm * 32 + mt * 16 + gid + r2 * 8;
            int b = m >> 11;
            int l = m & (SEQ - 1);
            float* orow = out + (((size_t)(b * N_HEADS + h)) * SEQ + l) * HEAD_DIM;
            #pragma unroll
            for (int nt = 0; nt < 4; nt++) {
                int col = wn * 32 + nt * 8 + tig * 2;
                float2 v;
                v.x = acc[mt][nt][r2 * 2 + 0] + bias[col];
                v.y = acc[mt][nt][r2 * 2 + 1] + bias[col + 1];
                *(float2*)(orow + col) = v;
            }
        }
    }
}

// ---------------------------------------------------------------------------
// RoPE on g_q / g_k. One thread per (bh, l, i) pair, i in [0,32).
// ---------------------------------------------------------------------------
__global__ __launch_bounds__(256) void rope_kernel()
{
    int idx = blockIdx.x * blockDim.x + threadIdx.x;
    int i  = idx & 31;
    int l  = (idx >> 5) & (SEQ - 1);
    int bh = idx >> 16;

    float inv_freq = __powf(10000.0f, -(float)i / 32.0f);
    float ang = (float)l * inv_freq;
    float s, c;
    __sincosf(ang, &s, &c);

    size_t base = ((size_t)bh * SEQ + l) * HEAD_DIM;
    float q1 = g_q[base + i], q2 = g_q[base + i + 32];
    g_q[base + i]      = q1 * c - q2 * s;
    g_q[base + i + 32] = q1 * s + q2 * c;
    float k1 = g_k[base + i], k2 = g_k[base + i + 32];
    g_k[base + i]      = k1 * c - k2 * s;
    g_k[base + i + 32] = k1 * s + k2 * c;
}

// ---------------------------------------------------------------------------
// Flash attention, tf32 tensor cores.
// Br=64 queries per block (4 warps x 16 rows), Bc=64 keys per tile.
// K smem tile is reused to hold P (K is dead after S is computed).
// ---------------------------------------------------------------------------
__global__ __launch_bounds__(128) void attn_tc()
{
    __shared__ uint32_t KP[64][68];   // K tile [key][dim], then P [query][key]
    __shared__ uint32_t Vs[64][68];   // V tile [key][dim]

    const int tid  = threadIdx.x;
    const int warp = tid >> 5;
    const int lane = tid & 31;
    const int gid  = lane >> 2;
    const int tig  = lane & 3;
    const int bh   = blockIdx.y;
    const int q0   = blockIdx.x * 64 + warp * 16;

    // Q fragments in registers, pre-scaled by 1/sqrt(64)
    const float* qr0 = g_q + ((size_t)bh * SEQ + q0 + gid) * HEAD_DIM;
    const float* qr1 = qr0 + 8 * HEAD_DIM;
    uint32_t qa[8][4];
    #pragma unroll
    for (int ks = 0; ks < 8; ks++) {
        qa[ks][0] = f2t(qr0[ks * 8 + tig] * 0.125f);
        qa[ks][1] = f2t(qr1[ks * 8 + tig] * 0.125f);
        qa[ks][2] = f2t(qr0[ks * 8 + tig + 4] * 0.125f);
        qa[ks][3] = f2t(qr1[ks * 8 + tig + 4] * 0.125f);
    }

    const float* kb = g_k + (size_t)bh * SEQ * HEAD_DIM;
    const float* vb = g_v + (size_t)bh * SEQ * HEAD_DIM;

    float oacc[8][4] = {};
    float mr0 = -1e30f, mr1 = -1e30f;
    float l0 = 0.0f, l1 = 0.0f;

    for (int t = 0; t < SEQ / 64; t++) {
        __syncthreads();
        // Load K, V tiles (64x64 each = 1024 float4 each; 8 per thread)
        #pragma unroll
        for (int i = 0; i < 8; i++) {
            int f = tid + i * 128;
            int r = f >> 4;
            int c = (f & 15) * 4;
            float4 k4 = *(const float4*)(kb + (size_t)(t * 64 + r) * HEAD_DIM + c);
            uint4 kt = { f2t(k4.x), f2t(k4.y), f2t(k4.z), f2t(k4.w) };
            *(uint4*)&KP[r][c] = kt;
            float4 v4 = *(const float4*)(vb + (size_t)(t * 64 + r) * HEAD_DIM + c);
            uint4 vt = { f2t(v4.x), f2t(v4.y), f2t(v4.z), f2t(v4.w) };
            *(uint4*)&Vs[r][c] = vt;
        }
        __syncthreads();

        // S = Q @ K^T   (M=16 per warp, N=64 keys, K=64 dims)
        float s[8][4] = {};
        #pragma unroll
        for (int ks = 0; ks < 8; ks++) {
            const int kk = ks * 8;
            #pragma unroll
            for (int nt = 0; nt < 8; nt++) {
                uint32_t b[2];
                b[0] = KP[nt * 8 + gid][kk + tig];
                b[1] = KP[nt * 8 + gid][kk + tig + 4];
                MMA_TF32(s[nt], qa[ks], b);
            }
        }

        // Online softmax (rows: q0+gid and q0+gid+8)
        float mx0 = -1e30f, mx1 = -1e30f;
        #pragma unroll
        for (int nt = 0; nt < 8; nt++) {
            mx0 = fmaxf(mx0, fmaxf(s[nt][0], s[nt][1]));
            mx1 = fmaxf(mx1, fmaxf(s[nt][2], s[nt][3]));
        }
        mx0 = fmaxf(mx0, __shfl_xor_sync(0xffffffff, mx0, 1));
        mx0 = fmaxf(mx0, __shfl_xor_sync(0xffffffff, mx0, 2));
        mx1 = fmaxf(mx1, __shfl_xor_sync(0xffffffff, mx1, 1));
        mx1 = fmaxf(mx1, __shfl_xor_sync(0xffffffff, mx1, 2));

        float nm0 = fmaxf(mr0, mx0);
        float nm1 = fmaxf(mr1, mx1);
        float cf0 = __expf(mr0 - nm0);
        float cf1 = __expf(mr1 - nm1);
        mr0 = nm0; mr1 = nm1;

        float rs0 = 0.0f, rs1 = 0.0f;
        #pragma unroll
        for (int nt = 0; nt < 8; nt++) {
            s[nt][0] = __expf(s[nt][0] - nm0);
            s[nt][1] = __expf(s[nt][1] - nm0);
            s[nt][2] = __expf(s[nt][2] - nm1);
            s[nt][3] = __expf(s[nt][3] - nm1);
            rs0 += s[nt][0] + s[nt][1];
            rs1 += s[nt][2] + s[nt][3];
        }
        rs0 += __shfl_xor_sync(0xffffffff, rs0, 1);
        rs0 += __shfl_xor_sync(0xffffffff, rs0, 2);
        rs1 += __shfl_xor_sync(0xffffffff, rs1, 1);
        rs1 += __shfl_xor_sync(0xffffffff, rs1, 2);
        l0 = l0 * cf0 + rs0;
        l1 = l1 * cf1 + rs1;

        #pragma unroll
        for (int nt = 0; nt < 8; nt++) {
            oacc[nt][0] *= cf0; oacc[nt][1] *= cf0;
            oacc[nt][2] *= cf1; oacc[nt][3] *= cf1;
        }

        __syncthreads();   // everyone done reading K before overwrite with P
        // Store P (tf32) into KP as [query][key]
        const int pr0 = warp * 16 + gid;
        #pragma unroll
        for (int nt = 0; nt < 8; nt++) {
            int col = nt * 8 + tig * 2;
            KP[pr0][col]         = f2t(s[nt][0]);
            KP[pr0][col + 1]     = f2t(s[nt][1]);
            KP[pr0 + 8][col]     = f2t(s[nt][2]);
            KP[pr0 + 8][col + 1] = f2t(s[nt][3]);
        }
        __syncthreads();

        // O += P @ V   (M=16 per warp, N=64 dims, K=64 keys)
        #pragma unroll
        for (int ks = 0; ks < 8; ks++) {
            const int kk = ks * 8;
            uint32_t pa[4];
            pa[0] = KP[pr0][kk + tig];
            pa[1] = KP[pr0 + 8][kk + tig];
            pa[2] = KP[pr0][kk + tig + 4];
            pa[3] = KP[pr0 + 8][kk + tig + 4];
            #pragma unroll
            for (int nt = 0; nt < 8; nt++) {
                uint32_t vbf[2];
                vbf[0] = Vs[kk + tig][nt * 8 + gid];
                vbf[1] = Vs[kk + tig + 4][nt * 8 + gid];
                MMA_TF32(oacc[nt], pa, vbf);
            }
        }
    }

    // Normalize + write merged ctx [b*SEQ+l][h*64+col]
    float inv0 = 1.0f / l0;
    float inv1 = 1.0f / l1;
    int b = bh >> 4;
    int h = bh & 15;
    int row0 = blockIdx.x * 64 + warp * 16 + gid;
    float* o0 = g_ctx + ((size_t)(b * SEQ + row0)) * D_MODEL + h * HEAD_DIM;
    float* o1 = g_ctx + ((size_t)(b * SEQ + row0 + 8)) * D_MODEL + h * HEAD_DIM;
    #pragma unroll
    for (int nt = 0; nt < 8; nt++) {
        int col = nt * 8 + tig * 2;
        float2 v0 = { oacc[nt][0] * inv0, oacc[nt][1] * inv0 };
        float2 v1 = { oacc[nt][2] * inv1, oacc[nt][3] * inv1 };
        *(float2*)(o0 + col) = v0;
        *(float2*)(o1 + col) = v1;
    }
}

// ---------------------------------------------------------------------------
// Output projection (tf32): out[8192x1024] = ctx @ Wo + bo
// Same tiling as qkv_gemm_tc. Grid (64, 16).
// ---------------------------------------------------------------------------
__global__ __launch_bounds__(256) void out_gemm_tc(
    const float* __restrict__ Wo, const float* __restrict__ bo,
    float* __restrict__ out)
{
    __shared__ uint32_t As[128][36];
    __shared__ uint32_t Bs[32][68];

    const int tid  = threadIdx.x;
    const int warp = tid >> 5;
    const int lane = tid & 31;
    const int wm   = warp >> 1;
    const int wn   = warp & 1;
    const int gid  = lane >> 2;
    const int tig  = lane & 3;
    const int m0   = blockIdx.x * 128;
    const int n0   = blockIdx.y * 64;

    float acc[2][4][4] = {};

    for (int k0 = 0; k0 < D_MODEL; k0 += 32) {
        __syncthreads();
        #pragma unroll
        for (int i = 0; i < 4; i++) {
            int f = tid + i * 256;
            int r = f >> 3;
            int c = (f & 7) * 4;
            float4 a = *(const float4*)(g_ctx + (size_t)(m0 + r) * D_MODEL + k0 + c);
            uint4 t = { f2t(a.x), f2t(a.y), f2t(a.z), f2t(a.w) };
            *(uint4*)&As[r][c] = t;
        }
        #pragma unroll
        for (int i = 0; i < 2; i++) {
            int f = tid + i * 256;
            int r = f >> 4;
            int c = (f & 15) * 4;
            float4 b = *(const float4*)(Wo + (size_t)(k0 + r) * D_MODEL + n0 + c);
            uint4 t = { f2t(b.x), f2t(b.y), f2t(b.z), f2t(b.w) };
            *(uint4*)&Bs[r][c] = t;
        }
        __syncthreads();

        #pragma unroll
        for (int ks = 0; ks < 4; ks++) {
            const int kk = ks * 8;
            uint32_t a[2][4], b[4][2];
            #pragma unroll
            for (int mt = 0; mt < 2; mt++) {
                const int mr = wm * 32 + mt * 16;
                a[mt][0] = As[mr + gid][kk + tig];
                a[mt][1] = As[mr + gid + 8][kk + tig];
                a[mt][2] = As[mr + gid][kk + tig + 4];
                a[mt][3] = As[mr + gid + 8][kk + tig + 4];
            }
            #pragma unroll
            for (int nt = 0; nt < 4; nt++) {
                const int nc = wn * 32 + nt * 8;
                b[nt][0] = Bs[kk + tig][nc + gid];
                b[nt][1] = Bs[kk + tig + 4][nc + gid];
            }
            #pragma unroll
            for (int mt = 0; mt < 2; mt++)
                #pragma unroll
                for (int nt = 0; nt < 4; nt++)
                    MMA_TF32(acc[mt][nt], a[mt], b[nt]);
        }
    }

    #pragma unroll
    for (int mt = 0; mt < 2; mt++) {
        #pragma unroll
        for (int r2 = 0; r2 < 2; r2++) {
            int m = m0 + wm * 32 + mt * 16 + gid + r2 * 8;
            #pragma unroll
            for (int nt = 0; nt < 4; nt++) {
                int n = n0 + wn * 32 + nt * 8 + tig * 2;
                float2 v;
                v.x = acc[mt][nt][r2 * 2 + 0] + bo[n];
                v.y = acc[mt][nt][r2 * 2 + 1] + bo[n + 1];
                *(float2*)(out + (size_t)m * D_MODEL + n) = v;
            }
        }
    }
}

// ---------------------------------------------------------------------------
extern "C" void kernel_launch(void* const* d_in, const int* in_sizes, int n_in,
                              void* d_out, int out_size)
{
    const float* x  = (const float*)d_in[0];
    const float* Wq = (const float*)d_in[1];
    const float* bq = (const float*)d_in[2];
    const float* Wk = (const float*)d_in[3];
    const float* bk = (const float*)d_in[4];
    const float* Wv = (const float*)d_in[5];
    const float* bv = (const float*)d_in[6];
    const float* Wo = (const float*)d_in[7];
    const float* bo = (const float*)d_in[8];
    float* out = (float*)d_out;

    qkv_gemm_tc<<<dim3(M_TOT / 128, 48), 256>>>(x, Wq, bq, Wk, bk, Wv, bv);
    rope_kernel<<<(BATCH * N_HEADS * SEQ * 32) / 256, 256>>>();
    attn_tc<<<dim3(SEQ / 64, BATCH * N_HEADS), 128>>>();
    out_gemm_tc<<<dim3(M_TOT / 128, D_MODEL / 64), 256>>>(Wo, bo, out);
}